// round 16
// baseline (speedup 1.0000x reference)
#include <cuda_runtime.h>
#include <cuda_fp16.h>
#include <math.h>
#include <stdint.h>

// ---------------------------------------------------------------------------
// TemporalMamba on GB300 (compute_103-safe).
// R16: GEMMs consume pre-converted fp16 operands via a 4-stage cp.async
// pipeline (no in-loop convert, ~80 regs, 2 CTAs/SM). Producers emit fp16
// copies of activations; weights converted once up front.
// ---------------------------------------------------------------------------

#define IN_DIM_ 16384
#define DM_     512
#define DEPTH_  4
#define DI_     1024
#define DS_     16
#define DC_     4
#define DR_     32
#define B_      4
#define L_      256
#define T_      (B_ * L_)          // 1024 tokens
#define XPD_    (DR_ + 2 * DS_)    // 64

// fp32 scratch
__device__ __align__(128) float g_h[T_ * DM_];
__device__ __align__(128) float g_xz[T_ * 2 * DI_];
__device__ __align__(128) float g_xc[T_ * DI_];
__device__ __align__(128) float g_xdbl[T_ * XPD_];
__device__ __align__(128) float g_dt[T_ * DI_];
__device__ __align__(128) float g_hn[B_ * DM_];
__device__ __align__(128) float g_part[4 * T_ * DM_];

// fp16 operand buffers
__device__ __align__(128) __half g_x16[T_ * IN_DIM_];
__device__ __align__(128) __half g_inw16[DM_ * IN_DIM_];
__device__ __align__(128) __half g_minw16[DEPTH_ * 2 * DI_ * DM_];
__device__ __align__(128) __half g_xpw16[DEPTH_ * XPD_ * DI_];
__device__ __align__(128) __half g_moutw16[DEPTH_ * DM_ * DI_];
__device__ __align__(128) __half g_h16[T_ * DM_];
__device__ __align__(128) __half g_xc16[T_ * DI_];
__device__ __align__(128) __half g_y16[T_ * DI_];

// ---------------------------------------------------------------------------
// PTX helpers (baseline, legal on compute_103)
// ---------------------------------------------------------------------------
__device__ __forceinline__ uint32_t smem_u32(const void* p) {
    return (uint32_t)__cvta_generic_to_shared(p);
}

__device__ __forceinline__ void ldm4(uint32_t* r, uint32_t a) {
    asm volatile("ldmatrix.sync.aligned.m8n8.x4.shared.b16 {%0,%1,%2,%3}, [%4];"
                 : "=r"(r[0]), "=r"(r[1]), "=r"(r[2]), "=r"(r[3]) : "r"(a));
}

__device__ __forceinline__ void mma16816(float* c, const uint32_t* a, const uint32_t* b) {
    asm volatile("mma.sync.aligned.m16n8k16.row.col.f32.f16.f16.f32 "
                 "{%0,%1,%2,%3}, {%4,%5,%6,%7}, {%8,%9}, {%0,%1,%2,%3};"
                 : "+f"(c[0]), "+f"(c[1]), "+f"(c[2]), "+f"(c[3])
                 : "r"(a[0]), "r"(a[1]), "r"(a[2]), "r"(a[3]),
                   "r"(b[0]), "r"(b[1]));
}

__device__ __forceinline__ void cp16(uint32_t smem_dst, const void* gsrc) {
    asm volatile("cp.async.cg.shared.global [%0], [%1], 16;"
                 :: "r"(smem_dst), "l"(gsrc));
}
__device__ __forceinline__ void cp_commit() {
    asm volatile("cp.async.commit_group;");
}
template<int N> __device__ __forceinline__ void cp_wait() {
    asm volatile("cp.async.wait_group %0;" :: "n"(N));
}

// ---------------------------------------------------------------------------
// fp16 GEMM with cp.async pipeline: C(z-slab) = A16[M,K] * W16[N,K]^T.
// CTA: 128x64 tile, 256 threads = 8 warps (4m x 2n), BK=64, 4 stages.
// Requires M%128==0, N%64==0, kchunk%64==0.
// ---------------------------------------------------------------------------
#define STAGES 4
__global__ __launch_bounds__(256, 2) void hgemm(
    const __half* __restrict__ A, const __half* __restrict__ W,
    float* __restrict__ C, int M, int N, int K, int kchunk)
{
    constexpr int NT  = 64;
    constexpr int BK  = 64;
    constexpr int RP  = 72;                 // padded row (fp16) -> 144B
    constexpr int NFR = NT / 16;            // 4
    constexpr int SAE = 128 * RP;           // A halfs per stage
    constexpr int SWE = NT * RP;            // W halfs per stage
    constexpr int STE = SAE + SWE;          // halfs per stage

    extern __shared__ __half dsm[];

    const int tid  = threadIdx.x;
    const int wid  = tid >> 5;
    const int lane = tid & 31;
    const int wm   = wid & 3;
    const int wn   = wid >> 2;
    const int m0   = blockIdx.y * 128;
    const int n0   = blockIdx.x * NT;
    const int k0   = blockIdx.z * kchunk;
    const int nch  = kchunk / BK;
    const uint32_t ubase = smem_u32(dsm);

    float acc[2][NFR][4];
#pragma unroll
    for (int mi = 0; mi < 2; mi++)
#pragma unroll
        for (int ni = 0; ni < NFR; ni++)
#pragma unroll
            for (int j = 0; j < 4; j++) acc[mi][ni][j] = 0.f;

    // copy chunk cc into stage s (16B granules)
    auto copy_chunk = [&](int s, int cc) {
        const int kb = k0 + cc * BK;
        const uint32_t ua = ubase + (uint32_t)(s * STE) * 2;
        const uint32_t uw = ua + (uint32_t)SAE * 2;
#pragma unroll
        for (int i = 0; i < 4; i++) {           // A: 128x64 = 1024 granules
            const int idx = i * 256 + tid;
            const int row = idx >> 3, ch = idx & 7;
            cp16(ua + (uint32_t)(row * RP + ch * 8) * 2,
                 A + (size_t)(m0 + row) * K + kb + ch * 8);
        }
#pragma unroll
        for (int i = 0; i < 2; i++) {           // W: 64x64 = 512 granules
            const int idx = i * 256 + tid;
            const int row = idx >> 3, ch = idx & 7;
            cp16(uw + (uint32_t)(row * RP + ch * 8) * 2,
                 W + (size_t)(n0 + row) * K + kb + ch * 8);
        }
    };

    // prologue: stages 0..STAGES-2
#pragma unroll
    for (int s = 0; s < STAGES - 1; s++) {
        if (s < nch) copy_chunk(s, s);
        cp_commit();
    }

    for (int c = 0; c < nch; c++) {
        cp_wait<STAGES - 2>();
        __syncthreads();                         // chunk c resident; prior reads done

        {   // issue copy for chunk c+STAGES-1 (its buffer was last read at c-1)
            const int cn = c + STAGES - 1;
            if (cn < nch) copy_chunk(cn % STAGES, cn);
            cp_commit();
        }

        const uint32_t uA = ubase + (uint32_t)((c % STAGES) * STE) * 2;
        const uint32_t uW = uA + (uint32_t)SAE * 2;
#pragma unroll
        for (int ks = 0; ks < BK / 16; ks++) {
            uint32_t bh[NFR][2], af[2][4];
#pragma unroll
            for (int np = 0; np < NFR / 2; np++) {
                const int row = wn * (NT / 2) + np * 16 + (lane >> 4) * 8 + (lane & 7);
                const int col = ks * 16 + ((lane >> 3) & 1) * 8;
                uint32_t r[4];
                ldm4(r, uW + (uint32_t)(row * RP + col) * 2);
                bh[2 * np][0] = r[0]; bh[2 * np][1] = r[1];
                bh[2 * np + 1][0] = r[2]; bh[2 * np + 1][1] = r[3];
            }
#pragma unroll
            for (int mi = 0; mi < 2; mi++) {
                const int row = wm * 32 + mi * 16 + ((lane >> 3) & 1) * 8 + (lane & 7);
                const int col = ks * 16 + (lane >> 4) * 8;
                ldm4(af[mi], uA + (uint32_t)(row * RP + col) * 2);
            }
#pragma unroll
            for (int mi = 0; mi < 2; mi++)
#pragma unroll
                for (int ni = 0; ni < NFR; ni++)
                    mma16816(acc[mi][ni], af[mi], bh[ni]);
        }
    }

    // Epilogue: fragment layout direct to global (8B stores)
    float* Cp = C + (size_t)blockIdx.z * M * N;
    const int gid = lane >> 2, tig = lane & 3;
#pragma unroll
    for (int mi = 0; mi < 2; mi++) {
#pragma unroll
        for (int ni = 0; ni < NFR; ni++) {
            const int r  = m0 + wm * 32 + mi * 16 + gid;
            const int cc = n0 + wn * (NT / 2) + ni * 8 + tig * 2;
            float2 v0 = make_float2(acc[mi][ni][0], acc[mi][ni][1]);
            float2 v1 = make_float2(acc[mi][ni][2], acc[mi][ni][3]);
            *(float2*)&Cp[(size_t)r * N + cc]       = v0;
            *(float2*)&Cp[(size_t)(r + 8) * N + cc] = v1;
        }
    }
}

// ---------------------------------------------------------------------------
// Support kernels
// ---------------------------------------------------------------------------
__global__ void f2h_kernel(const float* __restrict__ s, __half* __restrict__ d, int n)
{
    const int i = (blockIdx.x * 256 + threadIdx.x) * 4;
    if (i >= n) return;
    const float4 f = *(const float4*)(s + i);
    *(__half2*)(d + i)     = __floats2half2_rn(f.x, f.y);
    *(__half2*)(d + i + 2) = __floats2half2_rn(f.z, f.w);
}

// Sum ks partials + optional bias; writes fp32 and (optionally) fp16 copy.
__global__ void reduce_kernel(const float* __restrict__ P, float* __restrict__ C,
                              __half* __restrict__ C16,
                              int MN, int ks, const float* __restrict__ bias, int N)
{
    const int i = blockIdx.x * 256 + threadIdx.x;
    if (i >= MN) return;
    float s = 0.f;
    for (int z = 0; z < ks; z++) s += P[(size_t)z * MN + i];
    if (bias) s += bias[i % N];
    C[i] = s;
    if (C16) C16[i] = __float2half(s);
}

__global__ void conv_silu_kernel(const float* __restrict__ cw, const float* __restrict__ cb)
{
    const int idx = blockIdx.x * 256 + threadIdx.x;   // T_*DI_ threads
    const int c = idx & (DI_ - 1);
    const int t = idx >> 10;
    const int b = t >> 8;
    const int l = t & (L_ - 1);
    float acc = cb[c];
#pragma unroll
    for (int k = 0; k < DC_; k++) {
        const int ls = l - (DC_ - 1) + k;
        if (ls >= 0)
            acc += g_xz[(size_t)((b << 8) + ls) * (2 * DI_) + c] * cw[c * DC_ + k];
    }
    const float v = acc / (1.f + __expf(-acc));
    g_xc[idx]   = v;
    g_xc16[idx] = __float2half(v);
}

__global__ void dt_kernel(const float* __restrict__ dw, const float* __restrict__ db)
{
    __shared__ float sx[DR_];
    const int t = blockIdx.y;
    const int d = blockIdx.x * 256 + threadIdx.x;
    if (threadIdx.x < DR_) sx[threadIdx.x] = g_xdbl[t * XPD_ + threadIdx.x];
    __syncthreads();
    float acc = db[d];
    const float4* w4 = (const float4*)(dw + (size_t)d * DR_);
#pragma unroll
    for (int r = 0; r < DR_ / 4; r++) {
        const float4 w = w4[r];
        acc += sx[4 * r] * w.x + sx[4 * r + 1] * w.y +
               sx[4 * r + 2] * w.z + sx[4 * r + 3] * w.w;
    }
    const float sp = (acc > 20.f) ? acc : log1pf(__expf(acc));
    g_dt[t * DI_ + d] = sp;
}

__global__ void scan_kernel(const float* __restrict__ Alog, const float* __restrict__ Dp)
{
    const int lane = threadIdx.x & 31;
    const int n    = lane & 15;
    const int p    = (((blockIdx.x * 256 + threadIdx.x) >> 5) << 1) + (lane >> 4);
    const int b    = p >> 10;
    const int d    = p & (DI_ - 1);

    const float A   = -__expf(Alog[d * DS_ + n]);
    const float Dpd = Dp[d];
    float s = 0.f;

    for (int l = 0; l < L_; l++) {
        const int t = (b << 8) + l;
        const float dtv = g_dt[t * DI_ + d];
        const float xv  = g_xc[t * DI_ + d];
        const float q   = __expf(dtv * A);
        const float bm  = g_xdbl[t * XPD_ + DR_ + n];
        s = q * s + (dtv * xv) * bm;
        float v = s * g_xdbl[t * XPD_ + DR_ + DS_ + n];
        v += __shfl_xor_sync(0xFFFFFFFFu, v, 8);
        v += __shfl_xor_sync(0xFFFFFFFFu, v, 4);
        v += __shfl_xor_sync(0xFFFFFFFFu, v, 2);
        v += __shfl_xor_sync(0xFFFFFFFFu, v, 1);
        if (n == 0) {
            const float zv = g_xz[(size_t)t * (2 * DI_) + DI_ + d];
            const float yy = v + xv * Dpd;
            g_y16[t * DI_ + d] = __float2half(yy * (zv / (1.f + __expf(-zv))));
        }
    }
}

__global__ void ln_kernel(const float* __restrict__ gamma, const float* __restrict__ beta)
{
    __shared__ float red[128];
    const int b   = blockIdx.x;
    const int tid = threadIdx.x;   // 128
    const float* row = g_h + (size_t)((b + 1) * L_ - 1) * DM_;

    float v[4]; float s = 0.f;
#pragma unroll
    for (int i = 0; i < 4; i++) { v[i] = row[tid + i * 128]; s += v[i]; }
    red[tid] = s; __syncthreads();
    for (int o = 64; o > 0; o >>= 1) { if (tid < o) red[tid] += red[tid + o]; __syncthreads(); }
    const float mu = red[0] * (1.f / DM_);
    __syncthreads();

    float var = 0.f;
#pragma unroll
    for (int i = 0; i < 4; i++) { const float dd = v[i] - mu; var += dd * dd; }
    red[tid] = var; __syncthreads();
    for (int o = 64; o > 0; o >>= 1) { if (tid < o) red[tid] += red[tid + o]; __syncthreads(); }
    const float rstd = rsqrtf(red[0] * (1.f / DM_) + 1e-5f);

#pragma unroll
    for (int i = 0; i < 4; i++) {
        const int m = tid + i * 128;
        g_hn[b * DM_ + m] = (v[i] - mu) * rstd * gamma[m] + beta[m];
    }
}

// Warp-per-output-row out-proj: coalesced out_w reads + shfl reduction.
__global__ void outproj_kernel(const float* __restrict__ ow, const float* __restrict__ ob,
                               float* __restrict__ out)
{
    __shared__ float sh[B_ * DM_];
    const int tid = threadIdx.x;  // 256
    for (int i = tid; i < B_ * DM_; i += 256) sh[i] = g_hn[i];
    __syncthreads();

    const int o    = blockIdx.x * 8 + (tid >> 5);
    const int lane = tid & 31;
    float a0 = 0.f, a1 = 0.f, a2 = 0.f, a3 = 0.f;
    const float* wr = ow + (size_t)o * DM_;
#pragma unroll
    for (int it = 0; it < DM_ / 128; it++) {
        const int m = it * 128 + lane * 4;
        const float4 w = *(const float4*)(wr + m);
        a0 += sh[0 * DM_ + m] * w.x + sh[0 * DM_ + m + 1] * w.y + sh[0 * DM_ + m + 2] * w.z + sh[0 * DM_ + m + 3] * w.w;
        a1 += sh[1 * DM_ + m] * w.x + sh[1 * DM_ + m + 1] * w.y + sh[1 * DM_ + m + 2] * w.z + sh[1 * DM_ + m + 3] * w.w;
        a2 += sh[2 * DM_ + m] * w.x + sh[2 * DM_ + m + 1] * w.y + sh[2 * DM_ + m + 2] * w.z + sh[2 * DM_ + m + 3] * w.w;
        a3 += sh[3 * DM_ + m] * w.x + sh[3 * DM_ + m + 1] * w.y + sh[3 * DM_ + m + 2] * w.z + sh[3 * DM_ + m + 3] * w.w;
    }
#pragma unroll
    for (int off = 16; off > 0; off >>= 1) {
        a0 += __shfl_xor_sync(0xFFFFFFFFu, a0, off);
        a1 += __shfl_xor_sync(0xFFFFFFFFu, a1, off);
        a2 += __shfl_xor_sync(0xFFFFFFFFu, a2, off);
        a3 += __shfl_xor_sync(0xFFFFFFFFu, a3, off);
    }
    if (lane == 0) {
        const float bo = ob[o];
        out[0 * IN_DIM_ + o] = a0 + bo;
        out[1 * IN_DIM_ + o] = a1 + bo;
        out[2 * IN_DIM_ + o] = a2 + bo;
        out[3 * IN_DIM_ + o] = a3 + bo;
    }
}

// ---------------------------------------------------------------------------
extern "C" void kernel_launch(void* const* d_in, const int* in_sizes, int n_in,
                              void* d_out, int out_size)
{
    const float* x       = (const float*)d_in[0];
    const float* in_w    = (const float*)d_in[1];
    const float* in_b    = (const float*)d_in[2];
    const float* ln_g    = (const float*)d_in[3];
    const float* ln_b    = (const float*)d_in[4];
    const float* out_w   = (const float*)d_in[5];
    const float* out_b   = (const float*)d_in[6];
    const float* m_in_w  = (const float*)d_in[7];
    const float* conv_w  = (const float*)d_in[8];
    const float* conv_b  = (const float*)d_in[9];
    const float* xproj_w = (const float*)d_in[10];
    const float* dt_w    = (const float*)d_in[11];
    const float* dt_b    = (const float*)d_in[12];
    const float* A_log   = (const float*)d_in[13];
    const float* D_p     = (const float*)d_in[14];
    const float* m_out_w = (const float*)d_in[15];
    float* outp = (float*)d_out;

    float *ph, *pxdbl, *ppart;
    __half *px16, *pinw16, *pminw16, *pxpw16, *pmoutw16, *ph16, *pxc16, *py16;
    cudaGetSymbolAddress((void**)&ph,      g_h);
    cudaGetSymbolAddress((void**)&pxdbl,   g_xdbl);
    cudaGetSymbolAddress((void**)&ppart,   g_part);
    cudaGetSymbolAddress((void**)&px16,    g_x16);
    cudaGetSymbolAddress((void**)&pinw16,  g_inw16);
    cudaGetSymbolAddress((void**)&pminw16, g_minw16);
    cudaGetSymbolAddress((void**)&pxpw16,  g_xpw16);
    cudaGetSymbolAddress((void**)&pmoutw16,g_moutw16);
    cudaGetSymbolAddress((void**)&ph16,    g_h16);
    cudaGetSymbolAddress((void**)&pxc16,   g_xc16);
    cudaGetSymbolAddress((void**)&py16,    g_y16);
    float* pxz; cudaGetSymbolAddress((void**)&pxz, g_xz);

    const int DSMEM = STAGES * (128 * 72 + 64 * 72) * 2;   // 110592 B
    static int attr_set = 0;
    if (!attr_set) {
        cudaFuncSetAttribute(hgemm, cudaFuncAttributeMaxDynamicSharedMemorySize, DSMEM);
        attr_set = 1;
    }

    // #1-#3: operand conversions needed before in-proj (hgemm is launch #4 for ncu)
    f2h_kernel<<<T_ * IN_DIM_ / 1024, 256>>>(x, px16, T_ * IN_DIM_);
    f2h_kernel<<<DM_ * IN_DIM_ / 1024, 256>>>(in_w, pinw16, DM_ * IN_DIM_);
    f2h_kernel<<<DEPTH_ * 2 * DI_ * DM_ / 1024, 256>>>(m_in_w, pminw16, DEPTH_ * 2 * DI_ * DM_);

    // h = x @ in_w^T + in_b   (M=1024, N=512, K=16384, z=4 -> 256 CTAs)
    hgemm<<<dim3(DM_ / 64, T_ / 128, 4), 256, DSMEM>>>(
        px16, pinw16, ppart, T_, DM_, IN_DIM_, IN_DIM_ / 4);

    // remaining weight conversions (independent of in-proj result)
    f2h_kernel<<<DEPTH_ * XPD_ * DI_ / 1024, 256>>>(xproj_w, pxpw16, DEPTH_ * XPD_ * DI_);
    f2h_kernel<<<DEPTH_ * DM_ * DI_ / 1024, 256>>>(m_out_w, pmoutw16, DEPTH_ * DM_ * DI_);

    reduce_kernel<<<(T_ * DM_ + 255) / 256, 256>>>(ppart, ph, ph16, T_ * DM_, 4, in_b, DM_);

    for (int i = 0; i < DEPTH_; i++) {
        // xz = h @ m_in_w[i]^T   (M=1024, N=2048, K=512) -> 256 CTAs, direct
        hgemm<<<dim3(2 * DI_ / 64, T_ / 128, 1), 256, DSMEM>>>(
            ph16, pminw16 + (size_t)i * 2 * DI_ * DM_, pxz, T_, 2 * DI_, DM_, DM_);

        // causal conv + silu (writes fp32 + fp16)
        conv_silu_kernel<<<T_ * DI_ / 256, 256>>>(conv_w + i * DI_ * DC_, conv_b + i * DI_);

        // xdbl = xc @ xproj_w[i]^T  (M=1024, N=64, K=1024, z=16 -> 128 CTAs)
        hgemm<<<dim3(1, T_ / 128, 16), 256, DSMEM>>>(
            pxc16, pxpw16 + (size_t)i * XPD_ * DI_, ppart, T_, XPD_, DI_, DI_ / 16);
        reduce_kernel<<<(T_ * XPD_ + 255) / 256, 256>>>(
            ppart, pxdbl, (__half*)nullptr, T_ * XPD_, 16, nullptr, XPD_);

        // dt = softplus(xdbl[:, :32] @ dt_w^T + dt_b)
        dt_kernel<<<dim3(DI_ / 256, T_), 256>>>(dt_w + (size_t)i * DI_ * DR_, dt_b + i * DI_);

        // selective scan + gating -> g_y16
        scan_kernel<<<(B_ * DI_ * DS_) / 256, 256>>>(A_log + (size_t)i * DI_ * DS_, D_p + i * DI_);

        // h = y @ m_out_w[i]^T   (M=1024, N=512, K=1024, z=4 -> 256 CTAs)
        hgemm<<<dim3(DM_ / 64, T_ / 128, 4), 256, DSMEM>>>(
            py16, pmoutw16 + (size_t)i * DM_ * DI_, ppart, T_, DM_, DI_, DI_ / 4);
        reduce_kernel<<<(T_ * DM_ + 255) / 256, 256>>>(ppart, ph, ph16, T_ * DM_, 4, nullptr, DM_);
    }

    // final layernorm on last token + output projection
    ln_kernel<<<B_, 128>>>(ln_g, ln_b);
    outproj_kernel<<<IN_DIM_ / 8, 256>>>(out_w, out_b, outp);
}

// round 17
// speedup vs baseline: 1.0270x; 1.0270x over previous
#include <cuda_runtime.h>
#include <cuda_fp16.h>
#include <math.h>
#include <stdint.h>

// ---------------------------------------------------------------------------
// TemporalMamba on GB300 (compute_103-safe).
// R17: cp.async fp16 GEMM pipeline (STAGES=3), NT=128 tile for the deep-K
// in-proj GEMM, and 16-elem/thread widened f2h + reduce kernels (the R16
// conversions ran at 1.3TB/s and ate the GEMM gains).
// ---------------------------------------------------------------------------

#define IN_DIM_ 16384
#define DM_     512
#define DEPTH_  4
#define DI_     1024
#define DS_     16
#define DC_     4
#define DR_     32
#define B_      4
#define L_      256
#define T_      (B_ * L_)          // 1024 tokens
#define XPD_    (DR_ + 2 * DS_)    // 64

// fp32 scratch
__device__ __align__(128) float g_h[T_ * DM_];
__device__ __align__(128) float g_xz[T_ * 2 * DI_];
__device__ __align__(128) float g_xc[T_ * DI_];
__device__ __align__(128) float g_xdbl[T_ * XPD_];
__device__ __align__(128) float g_dt[T_ * DI_];
__device__ __align__(128) float g_hn[B_ * DM_];
__device__ __align__(128) float g_part[8 * T_ * DM_];   // up to 8 K-slabs

// fp16 operand buffers
__device__ __align__(128) __half g_x16[T_ * IN_DIM_];
__device__ __align__(128) __half g_inw16[DM_ * IN_DIM_];
__device__ __align__(128) __half g_minw16[DEPTH_ * 2 * DI_ * DM_];
__device__ __align__(128) __half g_xpw16[DEPTH_ * XPD_ * DI_];
__device__ __align__(128) __half g_moutw16[DEPTH_ * DM_ * DI_];
__device__ __align__(128) __half g_h16[T_ * DM_];
__device__ __align__(128) __half g_xc16[T_ * DI_];
__device__ __align__(128) __half g_y16[T_ * DI_];

// ---------------------------------------------------------------------------
// PTX helpers (baseline, legal on compute_103)
// ---------------------------------------------------------------------------
__device__ __forceinline__ uint32_t smem_u32(const void* p) {
    return (uint32_t)__cvta_generic_to_shared(p);
}

__device__ __forceinline__ void ldm4(uint32_t* r, uint32_t a) {
    asm volatile("ldmatrix.sync.aligned.m8n8.x4.shared.b16 {%0,%1,%2,%3}, [%4];"
                 : "=r"(r[0]), "=r"(r[1]), "=r"(r[2]), "=r"(r[3]) : "r"(a));
}

__device__ __forceinline__ void mma16816(float* c, const uint32_t* a, const uint32_t* b) {
    asm volatile("mma.sync.aligned.m16n8k16.row.col.f32.f16.f16.f32 "
                 "{%0,%1,%2,%3}, {%4,%5,%6,%7}, {%8,%9}, {%0,%1,%2,%3};"
                 : "+f"(c[0]), "+f"(c[1]), "+f"(c[2]), "+f"(c[3])
                 : "r"(a[0]), "r"(a[1]), "r"(a[2]), "r"(a[3]),
                   "r"(b[0]), "r"(b[1]));
}

__device__ __forceinline__ void cp16(uint32_t smem_dst, const void* gsrc) {
    asm volatile("cp.async.cg.shared.global [%0], [%1], 16;"
                 :: "r"(smem_dst), "l"(gsrc));
}
__device__ __forceinline__ void cp_commit() {
    asm volatile("cp.async.commit_group;");
}
template<int N> __device__ __forceinline__ void cp_wait() {
    asm volatile("cp.async.wait_group %0;" :: "n"(N));
}

// ---------------------------------------------------------------------------
// fp16 GEMM with cp.async pipeline: C(z-slab) = A16[M,K] * W16[N,K]^T.
// CTA: 128 x NT tile, 256 threads = 8 warps (4m x 2n, warp tile 32 x NT/2),
// BK=64, 3 stages. Requires M%128==0, N%NT==0, kchunk%64==0.
// ---------------------------------------------------------------------------
#define STAGES 3
template<int NT>
__global__ __launch_bounds__(256, 2) void hgemm(
    const __half* __restrict__ A, const __half* __restrict__ W,
    float* __restrict__ C, int M, int N, int K, int kchunk)
{
    constexpr int BK  = 64;
    constexpr int RP  = 72;                 // padded row (fp16) -> 144B
    constexpr int NFR = NT / 16;            // n8-frags per warp
    constexpr int SAE = 128 * RP;           // A halfs per stage
    constexpr int SWE = NT * RP;            // W halfs per stage
    constexpr int STE = SAE + SWE;

    extern __shared__ __half dsm[];

    const int tid  = threadIdx.x;
    const int wid  = tid >> 5;
    const int lane = tid & 31;
    const int wm   = wid & 3;
    const int wn   = wid >> 2;
    const int m0   = blockIdx.y * 128;
    const int n0   = blockIdx.x * NT;
    const int k0   = blockIdx.z * kchunk;
    const int nch  = kchunk / BK;
    const uint32_t ubase = smem_u32(dsm);

    float acc[2][NFR][4];
#pragma unroll
    for (int mi = 0; mi < 2; mi++)
#pragma unroll
        for (int ni = 0; ni < NFR; ni++)
#pragma unroll
            for (int j = 0; j < 4; j++) acc[mi][ni][j] = 0.f;

    auto copy_chunk = [&](int s, int cc) {
        const int kb = k0 + cc * BK;
        const uint32_t ua = ubase + (uint32_t)(s * STE) * 2;
        const uint32_t uw = ua + (uint32_t)SAE * 2;
#pragma unroll
        for (int i = 0; i < 4; i++) {                 // A: 128x64 = 1024 granules
            const int idx = i * 256 + tid;
            const int row = idx >> 3, ch = idx & 7;
            cp16(ua + (uint32_t)(row * RP + ch * 8) * 2,
                 A + (size_t)(m0 + row) * K + kb + ch * 8);
        }
#pragma unroll
        for (int i = 0; i < NT / 32; i++) {           // W: NTx64 granules
            const int idx = i * 256 + tid;
            const int row = idx >> 3, ch = idx & 7;
            cp16(uw + (uint32_t)(row * RP + ch * 8) * 2,
                 W + (size_t)(n0 + row) * K + kb + ch * 8);
        }
    };

#pragma unroll
    for (int s = 0; s < STAGES - 1; s++) {
        if (s < nch) copy_chunk(s, s);
        cp_commit();
    }

    for (int c = 0; c < nch; c++) {
        cp_wait<STAGES - 2>();
        __syncthreads();

        {
            const int cn = c + STAGES - 1;
            if (cn < nch) copy_chunk(cn % STAGES, cn);
            cp_commit();
        }

        const uint32_t uA = ubase + (uint32_t)((c % STAGES) * STE) * 2;
        const uint32_t uW = uA + (uint32_t)SAE * 2;
#pragma unroll
        for (int ks = 0; ks < BK / 16; ks++) {
            uint32_t bh[NFR][2], af[2][4];
#pragma unroll
            for (int np = 0; np < NFR / 2; np++) {
                const int row = wn * (NT / 2) + np * 16 + (lane >> 4) * 8 + (lane & 7);
                const int col = ks * 16 + ((lane >> 3) & 1) * 8;
                uint32_t r[4];
                ldm4(r, uW + (uint32_t)(row * RP + col) * 2);
                bh[2 * np][0] = r[0]; bh[2 * np][1] = r[1];
                bh[2 * np + 1][0] = r[2]; bh[2 * np + 1][1] = r[3];
            }
#pragma unroll
            for (int mi = 0; mi < 2; mi++) {
                const int row = wm * 32 + mi * 16 + ((lane >> 3) & 1) * 8 + (lane & 7);
                const int col = ks * 16 + (lane >> 4) * 8;
                ldm4(af[mi], uA + (uint32_t)(row * RP + col) * 2);
            }
#pragma unroll
            for (int mi = 0; mi < 2; mi++)
#pragma unroll
                for (int ni = 0; ni < NFR; ni++)
                    mma16816(acc[mi][ni], af[mi], bh[ni]);
        }
    }

    float* Cp = C + (size_t)blockIdx.z * M * N;
    const int gid = lane >> 2, tig = lane & 3;
#pragma unroll
    for (int mi = 0; mi < 2; mi++) {
#pragma unroll
        for (int ni = 0; ni < NFR; ni++) {
            const int r  = m0 + wm * 32 + mi * 16 + gid;
            const int cc = n0 + wn * (NT / 2) + ni * 8 + tig * 2;
            float2 v0 = make_float2(acc[mi][ni][0], acc[mi][ni][1]);
            float2 v1 = make_float2(acc[mi][ni][2], acc[mi][ni][3]);
            *(float2*)&Cp[(size_t)r * N + cc]       = v0;
            *(float2*)&Cp[(size_t)(r + 8) * N + cc] = v1;
        }
    }
}

// ---------------------------------------------------------------------------
// Support kernels
// ---------------------------------------------------------------------------
// Widened f2h: 16 floats per thread (4 independent float4 chains).
__global__ void f2h_kernel(const float* __restrict__ s, __half* __restrict__ d, int n)
{
    const int i = (blockIdx.x * 256 + threadIdx.x) * 16;
    if (i >= n) return;
    float4 f0 = *(const float4*)(s + i);
    float4 f1 = *(const float4*)(s + i + 4);
    float4 f2 = *(const float4*)(s + i + 8);
    float4 f3 = *(const float4*)(s + i + 12);
    __half2 h[8];
    h[0] = __floats2half2_rn(f0.x, f0.y); h[1] = __floats2half2_rn(f0.z, f0.w);
    h[2] = __floats2half2_rn(f1.x, f1.y); h[3] = __floats2half2_rn(f1.z, f1.w);
    h[4] = __floats2half2_rn(f2.x, f2.y); h[5] = __floats2half2_rn(f2.z, f2.w);
    h[6] = __floats2half2_rn(f3.x, f3.y); h[7] = __floats2half2_rn(f3.z, f3.w);
    *(float4*)(d + i)     = *(float4*)(h);       // 16B = 8 halfs
    *(float4*)(d + i + 8) = *(float4*)(h + 4);
}

// Widened reduce: 4 outputs per thread, ks slabs + optional bias;
// writes fp32 and (optionally) fp16 copy. Requires MN%4==0, N%4==0.
__global__ void reduce_kernel(const float* __restrict__ P, float* __restrict__ C,
                              __half* __restrict__ C16,
                              int MN, int ks, const float* __restrict__ bias, int N)
{
    const int i = (blockIdx.x * 256 + threadIdx.x) * 4;
    if (i >= MN) return;
    float4 s = *(const float4*)(P + i);
    for (int z = 1; z < ks; z++) {
        const float4 p = *(const float4*)(P + (size_t)z * MN + i);
        s.x += p.x; s.y += p.y; s.z += p.z; s.w += p.w;
    }
    if (bias) {
        const float4 b = *(const float4*)(bias + (i % N));
        s.x += b.x; s.y += b.y; s.z += b.z; s.w += b.w;
    }
    *(float4*)(C + i) = s;
    if (C16) {
        __half2 h0 = __floats2half2_rn(s.x, s.y);
        __half2 h1 = __floats2half2_rn(s.z, s.w);
        *(__half2*)(C16 + i)     = h0;
        *(__half2*)(C16 + i + 2) = h1;
    }
}

__global__ void conv_silu_kernel(const float* __restrict__ cw, const float* __restrict__ cb)
{
    const int idx = blockIdx.x * 256 + threadIdx.x;   // T_*DI_ threads
    const int c = idx & (DI_ - 1);
    const int t = idx >> 10;
    const int b = t >> 8;
    const int l = t & (L_ - 1);
    float acc = cb[c];
#pragma unroll
    for (int k = 0; k < DC_; k++) {
        const int ls = l - (DC_ - 1) + k;
        if (ls >= 0)
            acc += g_xz[(size_t)((b << 8) + ls) * (2 * DI_) + c] * cw[c * DC_ + k];
    }
    const float v = acc / (1.f + __expf(-acc));
    g_xc[idx]   = v;
    g_xc16[idx] = __float2half(v);
}

__global__ void dt_kernel(const float* __restrict__ dw, const float* __restrict__ db)
{
    __shared__ float sx[DR_];
    const int t = blockIdx.y;
    const int d = blockIdx.x * 256 + threadIdx.x;
    if (threadIdx.x < DR_) sx[threadIdx.x] = g_xdbl[t * XPD_ + threadIdx.x];
    __syncthreads();
    float acc = db[d];
    const float4* w4 = (const float4*)(dw + (size_t)d * DR_);
#pragma unroll
    for (int r = 0; r < DR_ / 4; r++) {
        const float4 w = w4[r];
        acc += sx[4 * r] * w.x + sx[4 * r + 1] * w.y +
               sx[4 * r + 2] * w.z + sx[4 * r + 3] * w.w;
    }
    const float sp = (acc > 20.f) ? acc : log1pf(__expf(acc));
    g_dt[t * DI_ + d] = sp;
}

__global__ void scan_kernel(const float* __restrict__ Alog, const float* __restrict__ Dp)
{
    const int lane = threadIdx.x & 31;
    const int n    = lane & 15;
    const int p    = (((blockIdx.x * 256 + threadIdx.x) >> 5) << 1) + (lane >> 4);
    const int b    = p >> 10;
    const int d    = p & (DI_ - 1);

    const float A   = -__expf(Alog[d * DS_ + n]);
    const float Dpd = Dp[d];
    float s = 0.f;

    for (int l = 0; l < L_; l++) {
        const int t = (b << 8) + l;
        const float dtv = g_dt[t * DI_ + d];
        const float xv  = g_xc[t * DI_ + d];
        const float q   = __expf(dtv * A);
        const float bm  = g_xdbl[t * XPD_ + DR_ + n];
        s = q * s + (dtv * xv) * bm;
        float v = s * g_xdbl[t * XPD_ + DR_ + DS_ + n];
        v += __shfl_xor_sync(0xFFFFFFFFu, v, 8);
        v += __shfl_xor_sync(0xFFFFFFFFu, v, 4);
        v += __shfl_xor_sync(0xFFFFFFFFu, v, 2);
        v += __shfl_xor_sync(0xFFFFFFFFu, v, 1);
        if (n == 0) {
            const float zv = g_xz[(size_t)t * (2 * DI_) + DI_ + d];
            const float yy = v + xv * Dpd;
            g_y16[t * DI_ + d] = __float2half(yy * (zv / (1.f + __expf(-zv))));
        }
    }
}

__global__ void ln_kernel(const float* __restrict__ gamma, const float* __restrict__ beta)
{
    __shared__ float red[128];
    const int b   = blockIdx.x;
    const int tid = threadIdx.x;   // 128
    const float* row = g_h + (size_t)((b + 1) * L_ - 1) * DM_;

    float v[4]; float s = 0.f;
#pragma unroll
    for (int i = 0; i < 4; i++) { v[i] = row[tid + i * 128]; s += v[i]; }
    red[tid] = s; __syncthreads();
    for (int o = 64; o > 0; o >>= 1) { if (tid < o) red[tid] += red[tid + o]; __syncthreads(); }
    const float mu = red[0] * (1.f / DM_);
    __syncthreads();

    float var = 0.f;
#pragma unroll
    for (int i = 0; i < 4; i++) { const float dd = v[i] - mu; var += dd * dd; }
    red[tid] = var; __syncthreads();
    for (int o = 64; o > 0; o >>= 1) { if (tid < o) red[tid] += red[tid + o]; __syncthreads(); }
    const float rstd = rsqrtf(red[0] * (1.f / DM_) + 1e-5f);

#pragma unroll
    for (int i = 0; i < 4; i++) {
        const int m = tid + i * 128;
        g_hn[b * DM_ + m] = (v[i] - mu) * rstd * gamma[m] + beta[m];
    }
}

// Warp-per-output-row out-proj: coalesced out_w reads + shfl reduction.
__global__ void outproj_kernel(const float* __restrict__ ow, const float* __restrict__ ob,
                               float* __restrict__ out)
{
    __shared__ float sh[B_ * DM_];
    const int tid = threadIdx.x;  // 256
    for (int i = tid; i < B_ * DM_; i += 256) sh[i] = g_hn[i];
    __syncthreads();

    const int o    = blockIdx.x * 8 + (tid >> 5);
    const int lane = tid & 31;
    float a0 = 0.f, a1 = 0.f, a2 = 0.f, a3 = 0.f;
    const float* wr = ow + (size_t)o * DM_;
#pragma unroll
    for (int it = 0; it < DM_ / 128; it++) {
        const int m = it * 128 + lane * 4;
        const float4 w = *(const float4*)(wr + m);
        a0 += sh[0 * DM_ + m] * w.x + sh[0 * DM_ + m + 1] * w.y + sh[0 * DM_ + m + 2] * w.z + sh[0 * DM_ + m + 3] * w.w;
        a1 += sh[1 * DM_ + m] * w.x + sh[1 * DM_ + m + 1] * w.y + sh[1 * DM_ + m + 2] * w.z + sh[1 * DM_ + m + 3] * w.w;
        a2 += sh[2 * DM_ + m] * w.x + sh[2 * DM_ + m + 1] * w.y + sh[2 * DM_ + m + 2] * w.z + sh[2 * DM_ + m + 3] * w.w;
        a3 += sh[3 * DM_ + m] * w.x + sh[3 * DM_ + m + 1] * w.y + sh[3 * DM_ + m + 2] * w.z + sh[3 * DM_ + m + 3] * w.w;
    }
#pragma unroll
    for (int off = 16; off > 0; off >>= 1) {
        a0 += __shfl_xor_sync(0xFFFFFFFFu, a0, off);
        a1 += __shfl_xor_sync(0xFFFFFFFFu, a1, off);
        a2 += __shfl_xor_sync(0xFFFFFFFFu, a2, off);
        a3 += __shfl_xor_sync(0xFFFFFFFFu, a3, off);
    }
    if (lane == 0) {
        const float bo = ob[o];
        out[0 * IN_DIM_ + o] = a0 + bo;
        out[1 * IN_DIM_ + o] = a1 + bo;
        out[2 * IN_DIM_ + o] = a2 + bo;
        out[3 * IN_DIM_ + o] = a3 + bo;
    }
}

// ---------------------------------------------------------------------------
extern "C" void kernel_launch(void* const* d_in, const int* in_sizes, int n_in,
                              void* d_out, int out_size)
{
    const float* x       = (const float*)d_in[0];
    const float* in_w    = (const float*)d_in[1];
    const float* in_b    = (const float*)d_in[2];
    const float* ln_g    = (const float*)d_in[3];
    const float* ln_b    = (const float*)d_in[4];
    const float* out_w   = (const float*)d_in[5];
    const float* out_b   = (const float*)d_in[6];
    const float* m_in_w  = (const float*)d_in[7];
    const float* conv_w  = (const float*)d_in[8];
    const float* conv_b  = (const float*)d_in[9];
    const float* xproj_w = (const float*)d_in[10];
    const float* dt_w    = (const float*)d_in[11];
    const float* dt_b    = (const float*)d_in[12];
    const float* A_log   = (const float*)d_in[13];
    const float* D_p     = (const float*)d_in[14];
    const float* m_out_w = (const float*)d_in[15];
    float* outp = (float*)d_out;

    float *ph, *pxdbl, *ppart, *pxz;
    __half *px16, *pinw16, *pminw16, *pxpw16, *pmoutw16, *ph16, *pxc16, *py16;
    cudaGetSymbolAddress((void**)&ph,      g_h);
    cudaGetSymbolAddress((void**)&pxdbl,   g_xdbl);
    cudaGetSymbolAddress((void**)&ppart,   g_part);
    cudaGetSymbolAddress((void**)&pxz,     g_xz);
    cudaGetSymbolAddress((void**)&px16,    g_x16);
    cudaGetSymbolAddress((void**)&pinw16,  g_inw16);
    cudaGetSymbolAddress((void**)&pminw16, g_minw16);
    cudaGetSymbolAddress((void**)&pxpw16,  g_xpw16);
    cudaGetSymbolAddress((void**)&pmoutw16,g_moutw16);
    cudaGetSymbolAddress((void**)&ph16,    g_h16);
    cudaGetSymbolAddress((void**)&pxc16,   g_xc16);
    cudaGetSymbolAddress((void**)&py16,    g_y16);

    const int DS128 = STAGES * (128 + 128) * 72 * 2;   // 110592 B
    const int DS64  = STAGES * (128 + 64) * 72 * 2;    //  82944 B
    static int attr_set = 0;
    if (!attr_set) {
        cudaFuncSetAttribute(hgemm<128>, cudaFuncAttributeMaxDynamicSharedMemorySize, DS128);
        cudaFuncSetAttribute(hgemm<64>,  cudaFuncAttributeMaxDynamicSharedMemorySize, DS64);
        attr_set = 1;
    }

    // operand conversions (widened: 4096 elems per 256-thread CTA)
    f2h_kernel<<<T_ * IN_DIM_ / 4096, 256>>>(x, px16, T_ * IN_DIM_);
    f2h_kernel<<<DM_ * IN_DIM_ / 4096, 256>>>(in_w, pinw16, DM_ * IN_DIM_);
    f2h_kernel<<<DEPTH_ * 2 * DI_ * DM_ / 4096, 256>>>(m_in_w, pminw16, DEPTH_ * 2 * DI_ * DM_);

    // h = x @ in_w^T + in_b  (M=1024, N=512, K=16384; NT=128, z=8 -> 256 CTAs)
    hgemm<128><<<dim3(DM_ / 128, T_ / 128, 8), 256, DS128>>>(
        px16, pinw16, ppart, T_, DM_, IN_DIM_, IN_DIM_ / 8);

    // remaining weight conversions (independent of in-proj result)
    f2h_kernel<<<DEPTH_ * XPD_ * DI_ / 4096, 256>>>(xproj_w, pxpw16, DEPTH_ * XPD_ * DI_);
    f2h_kernel<<<DEPTH_ * DM_ * DI_ / 4096, 256>>>(m_out_w, pmoutw16, DEPTH_ * DM_ * DI_);

    reduce_kernel<<<T_ * DM_ / 1024, 256>>>(ppart, ph, ph16, T_ * DM_, 8, in_b, DM_);

    for (int i = 0; i < DEPTH_; i++) {
        // xz = h @ m_in_w[i]^T  (M=1024, N=2048, K=512; NT=64 -> 256 CTAs, direct)
        hgemm<64><<<dim3(2 * DI_ / 64, T_ / 128, 1), 256, DS64>>>(
            ph16, pminw16 + (size_t)i * 2 * DI_ * DM_, pxz, T_, 2 * DI_, DM_, DM_);

        // causal conv + silu (writes fp32 + fp16)
        conv_silu_kernel<<<T_ * DI_ / 256, 256>>>(conv_w + i * DI_ * DC_, conv_b + i * DI_);

        // xdbl = xc @ xproj_w[i]^T  (M=1024, N=64, K=1024; NT=64, z=16 -> 128 CTAs)
        hgemm<64><<<dim3(1, T_ / 128, 16), 256, DS64>>>(
            pxc16, pxpw16 + (size_t)i * XPD_ * DI_, ppart, T_, XPD_, DI_, DI_ / 16);
        reduce_kernel<<<T_ * XPD_ / 1024, 256>>>(
            ppart, pxdbl, (__half*)nullptr, T_ * XPD_, 16, nullptr, XPD_);

        // dt = softplus(xdbl[:, :32] @ dt_w^T + dt_b)
        dt_kernel<<<dim3(DI_ / 256, T_), 256>>>(dt_w + (size_t)i * DI_ * DR_, dt_b + i * DI_);

        // selective scan + gating -> g_y16
        scan_kernel<<<(B_ * DI_ * DS_) / 256, 256>>>(A_log + (size_t)i * DI_ * DS_, D_p + i * DI_);

        // h = y @ m_out_w[i]^T  (M=1024, N=512, K=1024; NT=64, z=4 -> 256 CTAs)
        hgemm<64><<<dim3(DM_ / 64, T_ / 128, 4), 256, DS64>>>(
            py16, pmoutw16 + (size_t)i * DM_ * DI_, ppart, T_, DM_, DI_, DI_ / 4);
        reduce_kernel<<<T_ * DM_ / 1024, 256>>>(ppart, ph, ph16, T_ * DM_, 4, nullptr, DM_);
    }

    // final layernorm on last token + output projection
    ln_kernel<<<B_, 128>>>(ln_g, ln_b);
    outproj_kernel<<<IN_DIM_ / 8, 256>>>(out_w, out_b, outp);
}